// round 7
// baseline (speedup 1.0000x reference)
#include <cuda_runtime.h>

#define F_DIM 513
#define T_DIM 256
#define C_DIM 8
#define N_DIM 4
#define TSPLIT 16
#define TCHUNK (T_DIM / TSPLIT)   // 16
#define TF (T_DIM * F_DIM)        // 131328
#define NF (N_DIM * F_DIM)        // 2052
#define DIAG_LOAD 7.0710678118654755e-4f  // 0.001/sqrt(2)

// Partial Hermitian covariances: [input(2)][n(4)][chunk(16)][entry(64)][f(513)]
// entry 0..7 = diag (real), 8..35 = off-diag re (kk order), 36..63 = off-diag im
__device__ float g_partial[2 * N_DIM * TSPLIT * 64 * F_DIM];
// conj(W): [n][c][{re,im}][f]
__device__ float g_wc[N_DIM * C_DIM * 2 * F_DIM];

// -------------------------------------------------------------------------
// Pass 1: partial covariance — one thread per f, FULL 64-entry accumulator
// (zero redundant loads: each input value read exactly once chip-wide).
// Occupancy comes from the grid: (5, 16, 8) = 640 blocks of 128 thr,
// 5 blocks/SM (launch_bounds) -> ~20 warps/SM.
// -------------------------------------------------------------------------
__global__ __launch_bounds__(128, 5) void cov_partial_kernel(
    const float* __restrict__ target, const float* __restrict__ noise)
{
    int f = blockIdx.x * blockDim.x + threadIdx.x;
    if (f >= F_DIM) return;
    int nz  = blockIdx.z;
    int inp = nz & 1;
    int n   = nz >> 1;
    const float* src = inp ? noise : target;
    int t0 = blockIdx.y * TCHUNK;

    float d[8], orr[28], oii[28];
#pragma unroll
    for (int i = 0; i < 8; i++) d[i] = 0.f;
#pragma unroll
    for (int i = 0; i < 28; i++) { orr[i] = 0.f; oii[i] = 0.f; }

    // layout (N, 2, C, T, F): idx = (((n*2+ri)*8+c)*T + t)*F + f
    const float* baseR = src + (size_t)(16 * n) * TF + f;
    const float* baseI = src + (size_t)(16 * n + 8) * TF + f;

#pragma unroll 2
    for (int t = t0; t < t0 + TCHUNK; ++t) {
        int off = t * F_DIM;
        float xr[8], xi[8];
#pragma unroll
        for (int c = 0; c < 8; c++) {
            xr[c] = __ldg(baseR + (size_t)c * TF + off);
            xi[c] = __ldg(baseI + (size_t)c * TF + off);
        }
#pragma unroll
        for (int i = 0; i < 8; i++)
            d[i] = fmaf(xr[i], xr[i], fmaf(xi[i], xi[i], d[i]));
        int k = 0;
#pragma unroll
        for (int i = 0; i < 8; i++)
#pragma unroll
            for (int j = i + 1; j < 8; j++) {
                orr[k] = fmaf(xr[i], xr[j], fmaf(xi[i], xi[j], orr[k]));
                oii[k] = fmaf(xi[i], xr[j], fmaf(-xr[i], xi[j], oii[k]));
                k++;
            }
    }

    float* dst = g_partial +
        ((size_t)((inp * N_DIM + n) * TSPLIT + blockIdx.y) * 64) * F_DIM + f;
#pragma unroll
    for (int i = 0; i < 8; i++) dst[(size_t)i * F_DIM] = d[i];
#pragma unroll
    for (int k2 = 0; k2 < 28; k2++) {
        dst[(size_t)(8 + k2) * F_DIM]  = orr[k2];
        dst[(size_t)(36 + k2) * F_DIM] = oii[k2];
    }
}

// -------------------------------------------------------------------------
// Pass 2: per-(n,f) solve. Block = 256 thr = 32 matrices.
// Coalesced cooperative reduction of 16 chunks into smem, then 8-lane
// complex Gauss-Jordan per matrix.
// -------------------------------------------------------------------------
__global__ __launch_bounds__(256) void solve_kernel(const int* __restrict__ ref_idx)
{
    __shared__ float s_cov[2][64][33];   // [input][entry][matrix + pad]
    int tid = threadIdx.x;
    int m0  = blockIdx.x * 32;
    const float invT = 1.0f / (float)T_DIM;

    // 2*64*32 = 4096 outputs, 16 per thread; mi fastest -> coalesced f.
#pragma unroll
    for (int r = 0; r < 16; r++) {
        int o  = r * 256 + tid;
        int mi = o & 31;
        int e  = (o >> 5) & 63;
        int ip = o >> 11;
        int m  = min(m0 + mi, NF - 1);
        int n  = m / F_DIM, f = m % F_DIM;
        const float* base = g_partial +
            (size_t)((ip * N_DIM + n) * TSPLIT) * 64 * F_DIM +
            (size_t)e * F_DIM + f;
        float sv = 0.f;
#pragma unroll
        for (int ch = 0; ch < TSPLIT; ch++)
            sv += base[(size_t)ch * 64 * F_DIM];
        s_cov[ip][e][mi] = sv * invT;
    }
    __syncthreads();

    int mi = tid >> 3;
    int i  = tid & 7;
    int m  = min(m0 + mi, NF - 1);
    int n  = m / F_DIM, f = m % F_DIM;
    const unsigned FULL = 0xffffffffu;

    float nr[8], ni[8];
#pragma unroll
    for (int j = 0; j < 8; j++) {
        if (j == i) { nr[j] = s_cov[1][i][mi] + DIAG_LOAD; ni[j] = DIAG_LOAD; }
        else {
            int a = min(i, j), b = max(i, j);
            int kk = 7 * a - (a * (a - 1)) / 2 + (b - a - 1);
            float sign = (i < j) ? 1.f : -1.f;
            nr[j] = s_cov[1][8 + kk][mi];
            ni[j] = sign * s_cov[1][36 + kk][mi];
        }
    }

#pragma unroll
    for (int kp = 0; kp < 8; kp++) {
        float akk_r = __shfl_sync(FULL, nr[kp], kp, 8);
        float akk_i = __shfl_sync(FULL, ni[kp], kp, 8);
        float idn = 1.0f / fmaf(akk_r, akk_r, akk_i * akk_i);
        float p_r = akk_r * idn, p_i = -akk_i * idn;
        float s_r[8], s_i[8];
#pragma unroll
        for (int j = 0; j < 8; j++) {
            float ar = __shfl_sync(FULL, nr[j], kp, 8);
            float ai = __shfl_sync(FULL, ni[j], kp, 8);
            s_r[j] = ar * p_r - ai * p_i;
            s_i[j] = ar * p_i + ai * p_r;
        }
        if (i == kp) {
#pragma unroll
            for (int j = 0; j < 8; j++) { nr[j] = s_r[j]; ni[j] = s_i[j]; }
            nr[kp] = p_r; ni[kp] = p_i;
        } else {
            float f_r = nr[kp], f_i = ni[kp];
#pragma unroll
            for (int j = 0; j < 8; j++) {
                if (j == kp) continue;
                nr[j] -= f_r * s_r[j] - f_i * s_i[j];
                ni[j] -= f_r * s_i[j] + f_i * s_r[j];
            }
            nr[kp] = -(f_r * p_r - f_i * p_i);
            ni[kp] = -(f_r * p_i + f_i * p_r);
        }
    }

    float tr_[8], ti[8];
#pragma unroll
    for (int j = 0; j < 8; j++) {
        if (j == i) { tr_[j] = s_cov[0][i][mi]; ti[j] = 0.f; }
        else {
            int a = min(i, j), b = max(i, j);
            int kk = 7 * a - (a * (a - 1)) / 2 + (b - a - 1);
            float sign = (i < j) ? 1.f : -1.f;
            tr_[j] = s_cov[0][8 + kk][mi];
            ti[j]  = sign * s_cov[0][36 + kk][mi];
        }
    }

    float trc_r = 0.f, trc_i = 0.f;
#pragma unroll
    for (int j = 0; j < 8; j++) {
        trc_r += nr[j] * tr_[j] + ni[j] * ti[j];
        trc_i += ni[j] * tr_[j] - nr[j] * ti[j];
    }
#pragma unroll
    for (int off = 4; off > 0; off >>= 1) {
        trc_r += __shfl_xor_sync(FULL, trc_r, off, 8);
        trc_i += __shfl_xor_sync(FULL, trc_i, off, 8);
    }

    int ref = *ref_idx;
    float pr = 0.f, pi = 0.f;
#pragma unroll
    for (int jj = 0; jj < 8; jj++)
        if (jj == ref) { pr = tr_[jj]; pi = ti[jj]; }

    float w_r = 0.f, w_i = 0.f;
#pragma unroll
    for (int j = 0; j < 8; j++) {
        float br = __shfl_sync(FULL, pr, j, 8);
        float bi = __shfl_sync(FULL, pi, j, 8);
        w_r += nr[j] * br - ni[j] * bi;
        w_i += nr[j] * bi + ni[j] * br;
    }

    float ldn = 1.0f / fmaf(trc_r, trc_r, trc_i * trc_i);
    float lr = trc_r * ldn, li = -trc_i * ldn;
    float Wr = w_r * lr - w_i * li;
    float Wi = w_r * li + w_i * lr;

    g_wc[((n * 8 + i) * 2 + 0) * F_DIM + f] = Wr;
    g_wc[((n * 8 + i) * 2 + 1) * F_DIM + f] = -Wi;
}

// -------------------------------------------------------------------------
// Pass 3: beamform, loads for both t's hoisted ahead of FMAs (MLP=32).
// grid (5, 128, 4) = 2560 blocks of 128.
// -------------------------------------------------------------------------
#define TPER 2
__global__ __launch_bounds__(128) void beamform_kernel(
    const float* __restrict__ mix, float* __restrict__ out)
{
    int f = blockIdx.x * blockDim.x + threadIdx.x;
    if (f >= F_DIM) return;
    int n  = blockIdx.z;
    int t0 = blockIdx.y * TPER;

    float wr[8], wi[8];
#pragma unroll
    for (int c = 0; c < 8; c++) {
        wr[c] = g_wc[((n * 8 + c) * 2 + 0) * F_DIM + f];
        wi[c] = g_wc[((n * 8 + c) * 2 + 1) * F_DIM + f];
    }

    const float* baseR = mix + (size_t)(16 * n) * TF + f;
    const float* baseI = mix + (size_t)(16 * n + 8) * TF + f;
    float* outR = out + (size_t)(2 * n) * TF + f;      // (N,2,1,T,F)
    float* outI = out + (size_t)(2 * n + 1) * TF + f;

    float yr[TPER][8], yi[TPER][8];
#pragma unroll
    for (int dt = 0; dt < TPER; dt++) {
        int off = (t0 + dt) * F_DIM;
#pragma unroll
        for (int c = 0; c < 8; c++) {
            yr[dt][c] = __ldg(baseR + (size_t)c * TF + off);
            yi[dt][c] = __ldg(baseI + (size_t)c * TF + off);
        }
    }
#pragma unroll
    for (int dt = 0; dt < TPER; dt++) {
        float Xr = 0.f, Xi = 0.f;
#pragma unroll
        for (int c = 0; c < 8; c++) {
            Xr += wr[c] * yr[dt][c] - wi[c] * yi[dt][c];
            Xi += wr[c] * yi[dt][c] + wi[c] * yr[dt][c];
        }
        int off = (t0 + dt) * F_DIM;
        outR[off] = Xr;
        outI[off] = Xi;
    }
}

// -------------------------------------------------------------------------
extern "C" void kernel_launch(void* const* d_in, const int* in_sizes, int n_in,
                              void* d_out, int out_size)
{
    const float* mixture = (const float*)d_in[0];
    const float* target  = (const float*)d_in[1];
    const float* noise   = (const float*)d_in[2];
    const int*   ref     = (const int*)d_in[3];
    float* out = (float*)d_out;

    dim3 g1((F_DIM + 127) / 128, TSPLIT, N_DIM * 2);   // 5 x 16 x 8 = 640 blocks
    cov_partial_kernel<<<g1, 128>>>(target, noise);

    int groups = (NF + 31) / 32;
    solve_kernel<<<groups, 256>>>(ref);

    dim3 g3((F_DIM + 127) / 128, T_DIM / TPER, N_DIM);
    beamform_kernel<<<g3, 128>>>(mixture, out);
}

// round 8
// speedup vs baseline: 1.1353x; 1.1353x over previous
#include <cuda_runtime.h>

#define F_DIM 513
#define T_DIM 256
#define C_DIM 8
#define N_DIM 4
#define TSPLIT 14
#define TF (T_DIM * F_DIM)        // 131328
#define NF (N_DIM * F_DIM)        // 2052
#define DIAG_LOAD 7.0710678118654755e-4f  // 0.001/sqrt(2)

// Partial Hermitian covariances: [input(2)][n(4)][chunk(14)][entry(64)][f(513)]
// entry 0..7 = diag (real), 8..35 = off-diag re (kk order), 36..63 = off-diag im
__device__ float g_partial[2 * N_DIM * TSPLIT * 64 * F_DIM];
// conj(W): [n][c][{re,im}][f]
__device__ float g_wc[N_DIM * C_DIM * 2 * F_DIM];

// chunk boundaries for TSPLIT=14: 4 chunks of 19 t, 10 of 18 t
__device__ __forceinline__ int chunk_start(int y) { return y * 18 + min(y, 4); }

// -------------------------------------------------------------------------
// Pass 1: partial covariance — one thread per f, full 64-entry accumulator
// (zero redundant loads) + 1-deep software prefetch so the next t's 16
// loads are in flight during the current t's 128 FMAs.
// grid (5, 14, 8) = 560 blocks of 128 thr, 4 blocks/SM -> 16 warps/SM,
// single wave on 148 SMs.
// -------------------------------------------------------------------------
__global__ __launch_bounds__(128, 4) void cov_partial_kernel(
    const float* __restrict__ target, const float* __restrict__ noise)
{
    int f = blockIdx.x * blockDim.x + threadIdx.x;
    if (f >= F_DIM) return;
    int nz  = blockIdx.z;
    int inp = nz & 1;
    int n   = nz >> 1;
    const float* src = inp ? noise : target;
    int t0 = chunk_start(blockIdx.y);
    int t1 = chunk_start(blockIdx.y + 1);

    float d[8], orr[28], oii[28];
#pragma unroll
    for (int i = 0; i < 8; i++) d[i] = 0.f;
#pragma unroll
    for (int i = 0; i < 28; i++) { orr[i] = 0.f; oii[i] = 0.f; }

    // layout (N, 2, C, T, F): plane v = ri*8+c has stride TF
    const float* base = src + (size_t)(16 * n) * TF + f;

    float cur[16], nxt[16];
#pragma unroll
    for (int v = 0; v < 16; v++)
        cur[v] = __ldg(base + (size_t)v * TF + (size_t)t0 * F_DIM);

    for (int t = t0; t < t1; ++t) {
        if (t + 1 < t1) {
            int offn = (t + 1) * F_DIM;
#pragma unroll
            for (int v = 0; v < 16; v++)
                nxt[v] = __ldg(base + (size_t)v * TF + offn);
        }
        // FMAs on cur (xr = cur[0..7], xi = cur[8..15])
#pragma unroll
        for (int i = 0; i < 8; i++)
            d[i] = fmaf(cur[i], cur[i], fmaf(cur[8 + i], cur[8 + i], d[i]));
        int k = 0;
#pragma unroll
        for (int i = 0; i < 8; i++)
#pragma unroll
            for (int j = i + 1; j < 8; j++) {
                orr[k] = fmaf(cur[i], cur[j], fmaf(cur[8 + i], cur[8 + j], orr[k]));
                oii[k] = fmaf(cur[8 + i], cur[j], fmaf(-cur[i], cur[8 + j], oii[k]));
                k++;
            }
#pragma unroll
        for (int v = 0; v < 16; v++) cur[v] = nxt[v];
    }

    float* dst = g_partial +
        ((size_t)((inp * N_DIM + n) * TSPLIT + blockIdx.y) * 64) * F_DIM + f;
#pragma unroll
    for (int i = 0; i < 8; i++) dst[(size_t)i * F_DIM] = d[i];
#pragma unroll
    for (int k2 = 0; k2 < 28; k2++) {
        dst[(size_t)(8 + k2) * F_DIM]  = orr[k2];
        dst[(size_t)(36 + k2) * F_DIM] = oii[k2];
    }
}

// -------------------------------------------------------------------------
// Pass 2: per-(n,f) solve. Block = 256 thr = 8 matrices -> 257 blocks so
// the chunk reduction spreads across the whole chip. Reduction: 1024
// outputs, 4 per thread, 14 chunk loads each (32B-sector aligned).
// Solve phase: threads 0..63 (8 matrices x 8 lanes).
// -------------------------------------------------------------------------
__global__ __launch_bounds__(256) void solve_kernel(const int* __restrict__ ref_idx)
{
    __shared__ float s_cov[2][64][9];    // [input][entry][matrix + pad]
    int tid = threadIdx.x;
    int m0  = blockIdx.x * 8;
    const float invT = 1.0f / (float)T_DIM;

#pragma unroll
    for (int r = 0; r < 4; r++) {
        int o  = r * 256 + tid;
        int mi = o & 7;
        int e  = (o >> 3) & 63;
        int ip = o >> 9;
        int m  = min(m0 + mi, NF - 1);
        int n  = m / F_DIM, f = m % F_DIM;
        const float* base = g_partial +
            (size_t)((ip * N_DIM + n) * TSPLIT) * 64 * F_DIM +
            (size_t)e * F_DIM + f;
        float sv = 0.f;
#pragma unroll
        for (int ch = 0; ch < TSPLIT; ch++)
            sv += base[(size_t)ch * 64 * F_DIM];
        s_cov[ip][e][mi] = sv * invT;
    }
    __syncthreads();

    if (tid >= 64) return;
    int mi = tid >> 3;
    int i  = tid & 7;
    int m  = min(m0 + mi, NF - 1);
    int n  = m / F_DIM, f = m % F_DIM;
    const unsigned FULL = 0xffffffffu;

    float nr[8], ni[8];
#pragma unroll
    for (int j = 0; j < 8; j++) {
        if (j == i) { nr[j] = s_cov[1][i][mi] + DIAG_LOAD; ni[j] = DIAG_LOAD; }
        else {
            int a = min(i, j), b = max(i, j);
            int kk = 7 * a - (a * (a - 1)) / 2 + (b - a - 1);
            float sign = (i < j) ? 1.f : -1.f;
            nr[j] = s_cov[1][8 + kk][mi];
            ni[j] = sign * s_cov[1][36 + kk][mi];
        }
    }

#pragma unroll
    for (int kp = 0; kp < 8; kp++) {
        float akk_r = __shfl_sync(FULL, nr[kp], kp, 8);
        float akk_i = __shfl_sync(FULL, ni[kp], kp, 8);
        float idn = 1.0f / fmaf(akk_r, akk_r, akk_i * akk_i);
        float p_r = akk_r * idn, p_i = -akk_i * idn;
        float s_r[8], s_i[8];
#pragma unroll
        for (int j = 0; j < 8; j++) {
            float ar = __shfl_sync(FULL, nr[j], kp, 8);
            float ai = __shfl_sync(FULL, ni[j], kp, 8);
            s_r[j] = ar * p_r - ai * p_i;
            s_i[j] = ar * p_i + ai * p_r;
        }
        if (i == kp) {
#pragma unroll
            for (int j = 0; j < 8; j++) { nr[j] = s_r[j]; ni[j] = s_i[j]; }
            nr[kp] = p_r; ni[kp] = p_i;
        } else {
            float f_r = nr[kp], f_i = ni[kp];
#pragma unroll
            for (int j = 0; j < 8; j++) {
                if (j == kp) continue;
                nr[j] -= f_r * s_r[j] - f_i * s_i[j];
                ni[j] -= f_r * s_i[j] + f_i * s_r[j];
            }
            nr[kp] = -(f_r * p_r - f_i * p_i);
            ni[kp] = -(f_r * p_i + f_i * p_r);
        }
    }

    float tr_[8], ti[8];
#pragma unroll
    for (int j = 0; j < 8; j++) {
        if (j == i) { tr_[j] = s_cov[0][i][mi]; ti[j] = 0.f; }
        else {
            int a = min(i, j), b = max(i, j);
            int kk = 7 * a - (a * (a - 1)) / 2 + (b - a - 1);
            float sign = (i < j) ? 1.f : -1.f;
            tr_[j] = s_cov[0][8 + kk][mi];
            ti[j]  = sign * s_cov[0][36 + kk][mi];
        }
    }

    float trc_r = 0.f, trc_i = 0.f;
#pragma unroll
    for (int j = 0; j < 8; j++) {
        trc_r += nr[j] * tr_[j] + ni[j] * ti[j];
        trc_i += ni[j] * tr_[j] - nr[j] * ti[j];
    }
#pragma unroll
    for (int off = 4; off > 0; off >>= 1) {
        trc_r += __shfl_xor_sync(FULL, trc_r, off, 8);
        trc_i += __shfl_xor_sync(FULL, trc_i, off, 8);
    }

    int ref = *ref_idx;
    float pr = 0.f, pi = 0.f;
#pragma unroll
    for (int jj = 0; jj < 8; jj++)
        if (jj == ref) { pr = tr_[jj]; pi = ti[jj]; }

    float w_r = 0.f, w_i = 0.f;
#pragma unroll
    for (int j = 0; j < 8; j++) {
        float br = __shfl_sync(FULL, pr, j, 8);
        float bi = __shfl_sync(FULL, pi, j, 8);
        w_r += nr[j] * br - ni[j] * bi;
        w_i += nr[j] * bi + ni[j] * br;
    }

    float ldn = 1.0f / fmaf(trc_r, trc_r, trc_i * trc_i);
    float lr = trc_r * ldn, li = -trc_i * ldn;
    float Wr = w_r * lr - w_i * li;
    float Wi = w_r * li + w_i * lr;

    g_wc[((n * 8 + i) * 2 + 0) * F_DIM + f] = Wr;
    g_wc[((n * 8 + i) * 2 + 1) * F_DIM + f] = -Wi;
}

// -------------------------------------------------------------------------
// Pass 3: beamform, loads for both t's hoisted ahead of FMAs (MLP=32).
// grid (5, 128, 4) = 2560 blocks of 128.
// -------------------------------------------------------------------------
#define TPER 2
__global__ __launch_bounds__(128) void beamform_kernel(
    const float* __restrict__ mix, float* __restrict__ out)
{
    int f = blockIdx.x * blockDim.x + threadIdx.x;
    if (f >= F_DIM) return;
    int n  = blockIdx.z;
    int t0 = blockIdx.y * TPER;

    float wr[8], wi[8];
#pragma unroll
    for (int c = 0; c < 8; c++) {
        wr[c] = g_wc[((n * 8 + c) * 2 + 0) * F_DIM + f];
        wi[c] = g_wc[((n * 8 + c) * 2 + 1) * F_DIM + f];
    }

    const float* baseR = mix + (size_t)(16 * n) * TF + f;
    const float* baseI = mix + (size_t)(16 * n + 8) * TF + f;
    float* outR = out + (size_t)(2 * n) * TF + f;      // (N,2,1,T,F)
    float* outI = out + (size_t)(2 * n + 1) * TF + f;

    float yr[TPER][8], yi[TPER][8];
#pragma unroll
    for (int dt = 0; dt < TPER; dt++) {
        int off = (t0 + dt) * F_DIM;
#pragma unroll
        for (int c = 0; c < 8; c++) {
            yr[dt][c] = __ldg(baseR + (size_t)c * TF + off);
            yi[dt][c] = __ldg(baseI + (size_t)c * TF + off);
        }
    }
#pragma unroll
    for (int dt = 0; dt < TPER; dt++) {
        float Xr = 0.f, Xi = 0.f;
#pragma unroll
        for (int c = 0; c < 8; c++) {
            Xr += wr[c] * yr[dt][c] - wi[c] * yi[dt][c];
            Xi += wr[c] * yi[dt][c] + wi[c] * yr[dt][c];
        }
        int off = (t0 + dt) * F_DIM;
        outR[off] = Xr;
        outI[off] = Xi;
    }
}

// -------------------------------------------------------------------------
extern "C" void kernel_launch(void* const* d_in, const int* in_sizes, int n_in,
                              void* d_out, int out_size)
{
    const float* mixture = (const float*)d_in[0];
    const float* target  = (const float*)d_in[1];
    const float* noise   = (const float*)d_in[2];
    const int*   ref     = (const int*)d_in[3];
    float* out = (float*)d_out;

    dim3 g1((F_DIM + 127) / 128, TSPLIT, N_DIM * 2);   // 5 x 14 x 8 = 560 blocks
    cov_partial_kernel<<<g1, 128>>>(target, noise);

    int groups = (NF + 7) / 8;                          // 257 blocks
    solve_kernel<<<groups, 256>>>(ref);

    dim3 g3((F_DIM + 127) / 128, T_DIM / TPER, N_DIM);
    beamform_kernel<<<g3, 128>>>(mixture, out);
}

// round 9
// speedup vs baseline: 1.6150x; 1.4225x over previous
#include <cuda_runtime.h>

#define F_DIM 513
#define T_DIM 256
#define C_DIM 8
#define N_DIM 4
#define TF (T_DIM * F_DIM)        // 131328
#define NF (N_DIM * F_DIM)        // 2052
#define DIAG_LOAD 7.0710678118654755e-4f  // 0.001/sqrt(2)

// FINAL covariances (already /T): [input(2)][n(4)][entry(64)][f(513)]
// entry 0..7 = diag (real), 8..35 = off-diag re (kk order), 36..63 = off-diag im
__device__ float g_cov[2 * N_DIM * 64 * F_DIM];
// conj(W): [n][c][{re,im}][f]
__device__ float g_wc[N_DIM * C_DIM * 2 * F_DIM];

// -------------------------------------------------------------------------
// Pass 1 (fused): full covariance per (inp,n,f) in ONE block.
// Block 512 = 32 f x 16 t-slices (16 t each). Per thread: zero-redundancy
// 64-entry accumulator with 1-deep prefetch. Then 4 batches of 16 entries
// reduced across slices via smem; final /T store (no partial buffer).
// grid (17, 8) = 136 blocks, 1 block/SM, single wave.
// -------------------------------------------------------------------------
__global__ __launch_bounds__(512, 1) void cov_fused_kernel(
    const float* __restrict__ target, const float* __restrict__ noise)
{
    int fx = threadIdx.x & 31;          // f within block
    int sl = threadIdx.x >> 5;          // t-slice 0..15
    int gf = blockIdx.x * 32 + fx;
    int fc = min(gf, F_DIM - 1);
    int inp = blockIdx.y & 1;
    int n   = blockIdx.y >> 1;
    const float* src = inp ? noise : target;
    int t0 = sl * 16, t1 = t0 + 16;

    float d[8], orr[28], oii[28];
#pragma unroll
    for (int i = 0; i < 8; i++) d[i] = 0.f;
#pragma unroll
    for (int i = 0; i < 28; i++) { orr[i] = 0.f; oii[i] = 0.f; }

    // layout (N, 2, C, T, F): plane v = ri*8+c has stride TF
    const float* base = src + (size_t)(16 * n) * TF + fc;

    float cur[16], nxt[16];
#pragma unroll
    for (int v = 0; v < 16; v++)
        cur[v] = __ldg(base + (size_t)v * TF + (size_t)t0 * F_DIM);

#pragma unroll
    for (int t = t0; t < t1; ++t) {
        if (t + 1 < t1) {
            int offn = (t + 1) * F_DIM;
#pragma unroll
            for (int v = 0; v < 16; v++)
                nxt[v] = __ldg(base + (size_t)v * TF + offn);
        }
        // xr = cur[0..7], xi = cur[8..15]
#pragma unroll
        for (int i = 0; i < 8; i++)
            d[i] = fmaf(cur[i], cur[i], fmaf(cur[8 + i], cur[8 + i], d[i]));
        int k = 0;
#pragma unroll
        for (int i = 0; i < 8; i++)
#pragma unroll
            for (int j = i + 1; j < 8; j++) {
                orr[k] = fmaf(cur[i], cur[j], fmaf(cur[8 + i], cur[8 + j], orr[k]));
                oii[k] = fmaf(cur[8 + i], cur[j], fmaf(-cur[i], cur[8 + j], oii[k]));
                k++;
            }
#pragma unroll
        for (int v = 0; v < 16; v++) cur[v] = nxt[v];
    }

    // Cross-slice reduction, 4 batches of 16 entries. smem 32 KB.
    __shared__ float sred[16][16][32];   // [entry-in-batch][slice][f]
    float* gout = g_cov + (size_t)(inp * N_DIM + n) * 64 * F_DIM;
    const float invT = 1.0f / (float)T_DIM;

#pragma unroll
    for (int b = 0; b < 4; b++) {
#pragma unroll
        for (int q = 0; q < 16; q++) {
            int e = b * 16 + q;          // compile-time
            float v = (e < 8) ? d[e] : (e < 36 ? orr[e - 8] : oii[e - 36]);
            sred[q][sl][fx] = v;
        }
        __syncthreads();
        {
            int q = sl;                  // each thread one (e, f) output
            float sv = 0.f;
#pragma unroll
            for (int s = 0; s < 16; s++) sv += sred[q][s][fx];
            if (gf < F_DIM)
                gout[(size_t)(b * 16 + q) * F_DIM + gf] = sv * invT;
        }
        __syncthreads();
    }
}

// -------------------------------------------------------------------------
// Pass 2: per-(n,f) solve. Block = 256 thr = 8 matrices -> 257 blocks.
// Covariances are final; staging is one coalesced load per entry.
// Solve phase: threads 0..63 (8 matrices x 8 lanes), complex Gauss-Jordan.
// -------------------------------------------------------------------------
__global__ __launch_bounds__(256) void solve_kernel(const int* __restrict__ ref_idx)
{
    __shared__ float s_cov[2][64][9];    // [input][entry][matrix + pad]
    int tid = threadIdx.x;
    int m0  = blockIdx.x * 8;

#pragma unroll
    for (int r = 0; r < 4; r++) {
        int o  = r * 256 + tid;
        int mi = o & 7;
        int e  = (o >> 3) & 63;
        int ip = o >> 9;
        int m  = min(m0 + mi, NF - 1);
        int n  = m / F_DIM, f = m % F_DIM;
        s_cov[ip][e][mi] =
            g_cov[((size_t)(ip * N_DIM + n) * 64 + e) * F_DIM + f];
    }
    __syncthreads();

    if (tid >= 64) return;
    int mi = tid >> 3;
    int i  = tid & 7;
    int m  = min(m0 + mi, NF - 1);
    int n  = m / F_DIM, f = m % F_DIM;
    const unsigned FULL = 0xffffffffu;

    float nr[8], ni[8];
#pragma unroll
    for (int j = 0; j < 8; j++) {
        if (j == i) { nr[j] = s_cov[1][i][mi] + DIAG_LOAD; ni[j] = DIAG_LOAD; }
        else {
            int a = min(i, j), b = max(i, j);
            int kk = 7 * a - (a * (a - 1)) / 2 + (b - a - 1);
            float sign = (i < j) ? 1.f : -1.f;
            nr[j] = s_cov[1][8 + kk][mi];
            ni[j] = sign * s_cov[1][36 + kk][mi];
        }
    }

#pragma unroll
    for (int kp = 0; kp < 8; kp++) {
        float akk_r = __shfl_sync(FULL, nr[kp], kp, 8);
        float akk_i = __shfl_sync(FULL, ni[kp], kp, 8);
        float idn = 1.0f / fmaf(akk_r, akk_r, akk_i * akk_i);
        float p_r = akk_r * idn, p_i = -akk_i * idn;
        float s_r[8], s_i[8];
#pragma unroll
        for (int j = 0; j < 8; j++) {
            float ar = __shfl_sync(FULL, nr[j], kp, 8);
            float ai = __shfl_sync(FULL, ni[j], kp, 8);
            s_r[j] = ar * p_r - ai * p_i;
            s_i[j] = ar * p_i + ai * p_r;
        }
        if (i == kp) {
#pragma unroll
            for (int j = 0; j < 8; j++) { nr[j] = s_r[j]; ni[j] = s_i[j]; }
            nr[kp] = p_r; ni[kp] = p_i;
        } else {
            float f_r = nr[kp], f_i = ni[kp];
#pragma unroll
            for (int j = 0; j < 8; j++) {
                if (j == kp) continue;
                nr[j] -= f_r * s_r[j] - f_i * s_i[j];
                ni[j] -= f_r * s_i[j] + f_i * s_r[j];
            }
            nr[kp] = -(f_r * p_r - f_i * p_i);
            ni[kp] = -(f_r * p_i + f_i * p_r);
        }
    }

    float tr_[8], ti[8];
#pragma unroll
    for (int j = 0; j < 8; j++) {
        if (j == i) { tr_[j] = s_cov[0][i][mi]; ti[j] = 0.f; }
        else {
            int a = min(i, j), b = max(i, j);
            int kk = 7 * a - (a * (a - 1)) / 2 + (b - a - 1);
            float sign = (i < j) ? 1.f : -1.f;
            tr_[j] = s_cov[0][8 + kk][mi];
            ti[j]  = sign * s_cov[0][36 + kk][mi];
        }
    }

    float trc_r = 0.f, trc_i = 0.f;
#pragma unroll
    for (int j = 0; j < 8; j++) {
        trc_r += nr[j] * tr_[j] + ni[j] * ti[j];
        trc_i += ni[j] * tr_[j] - nr[j] * ti[j];
    }
#pragma unroll
    for (int off = 4; off > 0; off >>= 1) {
        trc_r += __shfl_xor_sync(FULL, trc_r, off, 8);
        trc_i += __shfl_xor_sync(FULL, trc_i, off, 8);
    }

    int ref = *ref_idx;
    float pr = 0.f, pi = 0.f;
#pragma unroll
    for (int jj = 0; jj < 8; jj++)
        if (jj == ref) { pr = tr_[jj]; pi = ti[jj]; }

    float w_r = 0.f, w_i = 0.f;
#pragma unroll
    for (int j = 0; j < 8; j++) {
        float br = __shfl_sync(FULL, pr, j, 8);
        float bi = __shfl_sync(FULL, pi, j, 8);
        w_r += nr[j] * br - ni[j] * bi;
        w_i += nr[j] * bi + ni[j] * br;
    }

    float ldn = 1.0f / fmaf(trc_r, trc_r, trc_i * trc_i);
    float lr = trc_r * ldn, li = -trc_i * ldn;
    float Wr = w_r * lr - w_i * li;
    float Wi = w_r * li + w_i * lr;

    g_wc[((n * 8 + i) * 2 + 0) * F_DIM + f] = Wr;
    g_wc[((n * 8 + i) * 2 + 1) * F_DIM + f] = -Wi;
}

// -------------------------------------------------------------------------
// Pass 3: beamform, loads for both t's hoisted ahead of FMAs (MLP=32).
// grid (5, 128, 4) = 2560 blocks of 128.
// -------------------------------------------------------------------------
#define TPER 2
__global__ __launch_bounds__(128) void beamform_kernel(
    const float* __restrict__ mix, float* __restrict__ out)
{
    int f = blockIdx.x * blockDim.x + threadIdx.x;
    if (f >= F_DIM) return;
    int n  = blockIdx.z;
    int t0 = blockIdx.y * TPER;

    float wr[8], wi[8];
#pragma unroll
    for (int c = 0; c < 8; c++) {
        wr[c] = g_wc[((n * 8 + c) * 2 + 0) * F_DIM + f];
        wi[c] = g_wc[((n * 8 + c) * 2 + 1) * F_DIM + f];
    }

    const float* baseR = mix + (size_t)(16 * n) * TF + f;
    const float* baseI = mix + (size_t)(16 * n + 8) * TF + f;
    float* outR = out + (size_t)(2 * n) * TF + f;      // (N,2,1,T,F)
    float* outI = out + (size_t)(2 * n + 1) * TF + f;

    float yr[TPER][8], yi[TPER][8];
#pragma unroll
    for (int dt = 0; dt < TPER; dt++) {
        int off = (t0 + dt) * F_DIM;
#pragma unroll
        for (int c = 0; c < 8; c++) {
            yr[dt][c] = __ldg(baseR + (size_t)c * TF + off);
            yi[dt][c] = __ldg(baseI + (size_t)c * TF + off);
        }
    }
#pragma unroll
    for (int dt = 0; dt < TPER; dt++) {
        float Xr = 0.f, Xi = 0.f;
#pragma unroll
        for (int c = 0; c < 8; c++) {
            Xr += wr[c] * yr[dt][c] - wi[c] * yi[dt][c];
            Xi += wr[c] * yi[dt][c] + wi[c] * yr[dt][c];
        }
        int off = (t0 + dt) * F_DIM;
        outR[off] = Xr;
        outI[off] = Xi;
    }
}

// -------------------------------------------------------------------------
extern "C" void kernel_launch(void* const* d_in, const int* in_sizes, int n_in,
                              void* d_out, int out_size)
{
    const float* mixture = (const float*)d_in[0];
    const float* target  = (const float*)d_in[1];
    const float* noise   = (const float*)d_in[2];
    const int*   ref     = (const int*)d_in[3];
    float* out = (float*)d_out;

    dim3 g1((F_DIM + 31) / 32, N_DIM * 2);   // 17 x 8 = 136 blocks
    cov_fused_kernel<<<g1, 512>>>(target, noise);

    int groups = (NF + 7) / 8;                // 257 blocks
    solve_kernel<<<groups, 256>>>(ref);

    dim3 g3((F_DIM + 127) / 128, T_DIM / TPER, N_DIM);
    beamform_kernel<<<g3, 128>>>(mixture, out);
}